// round 11
// baseline (speedup 1.0000x reference)
#include <cuda_runtime.h>
#include <cstddef>

typedef unsigned long long ull;

// ---------------- scratch (static device globals; no allocation) ----------------
__device__ float g_h64[4096 * 64];     // LSTM1 final hidden
__device__ float g_h256[4096 * 256];   // LSTM2 hidden

// ---------------- packed f32x2 helpers ----------------
__device__ __forceinline__ ull pk(float lo, float hi) {
    ull r;
    asm("mov.b64 %0, {%1, %2};" : "=l"(r) : "f"(lo), "f"(hi));
    return r;
}
__device__ __forceinline__ void fma2(ull& d, ull a, ull b) {
    asm("fma.rn.f32x2 %0, %1, %2, %0;" : "+l"(d) : "l"(a), "l"(b));
}
__device__ __forceinline__ float2 upk(ull v) {
    float2 r;
    asm("mov.b64 {%0, %1}, %2;" : "=f"(r.x), "=f"(r.y) : "l"(v));
    return r;
}

// accurate activations (expf ~2ulp) — measured rel_err 2e-6 with these
__device__ __forceinline__ float sigf(float x) {
    return __fdividef(1.0f, 1.0f + __expf(-x));
}
__device__ __forceinline__ float tanh_(float x) {
    return __fdividef(2.0f, 1.0f + __expf(-2.0f * x)) - 1.0f;
}

// ---------------- shared layout for LSTM1 (float offsets) ----------------
// Wq   float4[42][128]        : 21504 floats (k-pair packed weights)
// ACT  float4[2 grp][2 buf][42][17] : 4*714 float4 = 11424 floats
//      (act, k-pair packed + dup: {a[2k][b],a[2k][b],a[2k+1][b],a[2k+1][b]}, 16 batches + pad)
// bsh [256], eW [64]
#define S_WQ    0
#define S_ACT   21504
#define S_BSH   (S_ACT + 11424)      // 32928
#define S_EW    (S_BSH + 256)        // 33184
#define S_TOT   (S_EW + 64)          // 33248 floats = 132992 B
#define A2ROW   17                    // float4 per row (16 batches + 1 pad)
#define ABUF    714                   // float4 per buffer (42 * 17)

__global__ void __launch_bounds__(256, 1)
lstm1_kernel(const float* __restrict__ x,
             const float* __restrict__ W_embed,
             const float* __restrict__ Wih1,
             const float* __restrict__ Whh1,
             const float* __restrict__ b1)
{
    extern __shared__ float sm[];
    float4* Wq4  = reinterpret_cast<float4*>(sm + S_WQ);
    float4* ACT4 = reinterpret_cast<float4*>(sm + S_ACT);
    float*  bsh  = sm + S_BSH;
    float*  eW   = sm + S_EW;

    const int tid = threadIdx.x;
    const int bt  = blockIdx.x;          // batch tile (32 elems)

    // combined paired-k weight (gate order i|f|g|o)
    for (int idx = tid; idx < 42 * 128; idx += 256) {
        int kk = idx >> 7, pj = idx & 127;
        int g0 = 2 * pj;
        int k0 = 2 * kk, k1 = k0 + 1;
        float4 v;
        v.x = (k0 < 20) ? __ldg(&Wih1[g0 * 20 + k0])     : __ldg(&Whh1[g0 * 64 + (k0 - 20)]);
        v.y = (k0 < 20) ? __ldg(&Wih1[(g0+1) * 20 + k0]) : __ldg(&Whh1[(g0+1) * 64 + (k0 - 20)]);
        v.z = (k1 < 20) ? __ldg(&Wih1[g0 * 20 + k1])     : __ldg(&Whh1[g0 * 64 + (k1 - 20)]);
        v.w = (k1 < 20) ? __ldg(&Wih1[(g0+1) * 20 + k1]) : __ldg(&Whh1[(g0+1) * 64 + (k1 - 20)]);
        Wq4[idx] = v;
    }
    bsh[tid] = b1[tid];
    if (tid < 40) eW[tid] = W_embed[tid];
    // zero all act buffers (covers h rows of both groups' buffer 0)
    for (int idx = tid; idx < 4 * ABUF; idx += 256)
        ACT4[idx] = make_float4(0.f, 0.f, 0.f, 0.f);
    __syncthreads();

    // ---- mapping ----
    // warp w: group grp = w>>2 (16 batches), wl = w&3 -> j-sixteenth (16 j's per warp)
    // lane: jp = l&7 -> j-pair; bq = l>>3 -> batch quad (4 of 16)
    // Each warp covers its 16 j's ACROSS ALL 4 gate types for all 16 group batches:
    //   weight loads are 8-distinct-float4 (1 wf), act loads 4-distinct (1 wf).
    const int w   = tid >> 5, l = tid & 31;
    const int grp = w >> 2,  wl = w & 3;
    const int j0  = wl * 16 + 2 * (l & 7);   // gate index pair within 64-wide type
    const int b0  = 4 * (l >> 3);            // batch quad (within group)
    const int barid = 1 + grp;

    float4* actG0 = ACT4 + (grp * 2) * ABUF;       // buffer parity 0
    float4* actG1 = actG0 + ABUF;                  // buffer parity 1

    const float4* W4I = Wq4 + (wl * 8 + (l & 7));  // pj for type i
    const float4* W4F = W4I + 32;
    const float4* W4G = W4I + 64;
    const float4* W4O = W4I + 96;

    const ull bI = pk(bsh[j0],       bsh[j0 + 1]);
    const ull bF = pk(bsh[64 + j0],  bsh[64 + j0 + 1]);
    const ull bG = pk(bsh[128 + j0], bsh[128 + j0 + 1]);
    const ull bO = pk(bsh[192 + j0], bsh[192 + j0 + 1]);

    const int kkh = 10 + (j0 >> 1);      // h-row pair index for (j0, j0+1)

    // register-resident cell state
    float c0x=0.f,c0y=0.f,c1x=0.f,c1y=0.f,c2x=0.f,c2y=0.f,c3x=0.f,c3y=0.f;

    // embedding duty: warp wl owns group-local batches wl*4 .. wl*4+3
    const int eb0 = wl * 4;
    const float2* xrow = reinterpret_cast<const float2*>(x) +
                         (size_t)(bt * 32 + grp * 16 + eb0 + l) * 512;  // deref only l<4
    float2 tok = make_float2(0.f, 0.f), tok_nxt = make_float2(0.f, 0.f);
    if (l < 4) tok = xrow[0];
    // initial embedding (t=0) into group buffer 0
    {
        float* a0f = reinterpret_cast<float*>(actG0);
        #pragma unroll
        for (int b = 0; b < 4; b++) {
            float tx = __shfl_sync(0xffffffffu, tok.x, b);
            float ty = __shfl_sync(0xffffffffu, tok.y, b);
            if (l < 20) {
                float v = fmaxf(fmaf(tx, eW[2 * l], ty * eW[2 * l + 1]), 0.0f);
                *reinterpret_cast<float2*>(a0f + (l >> 1) * (A2ROW * 4) +
                                           (eb0 + b) * 4 + (l & 1) * 2) = make_float2(v, v);
            }
        }
    }
    if (l < 4) tok_nxt = xrow[1];
    asm volatile("bar.sync %0, 128;" :: "r"(barid) : "memory");

#define LOADP(wi,wf,wg,wo,a0,a1,a2,a3, kk) do {                                   \
    wi = *reinterpret_cast<const ulonglong2*>(W4I + (kk) * 128);                  \
    wf = *reinterpret_cast<const ulonglong2*>(W4F + (kk) * 128);                  \
    wg = *reinterpret_cast<const ulonglong2*>(W4G + (kk) * 128);                  \
    wo = *reinterpret_cast<const ulonglong2*>(W4O + (kk) * 128);                  \
    a0 = *reinterpret_cast<const ulonglong2*>(A4 + (kk) * A2ROW);                 \
    a1 = *reinterpret_cast<const ulonglong2*>(A4 + (kk) * A2ROW + 1);             \
    a2 = *reinterpret_cast<const ulonglong2*>(A4 + (kk) * A2ROW + 2);             \
    a3 = *reinterpret_cast<const ulonglong2*>(A4 + (kk) * A2ROW + 3);             \
} while (0)

#define COMPP(wi,wf,wg,wo,a0,a1,a2,a3) do {                                       \
    fma2(accI0, wi.x, a0.x); fma2(accI1, wi.x, a1.x);                             \
    fma2(accI2, wi.x, a2.x); fma2(accI3, wi.x, a3.x);                             \
    fma2(accF0, wf.x, a0.x); fma2(accF1, wf.x, a1.x);                             \
    fma2(accF2, wf.x, a2.x); fma2(accF3, wf.x, a3.x);                             \
    fma2(accG0, wg.x, a0.x); fma2(accG1, wg.x, a1.x);                             \
    fma2(accG2, wg.x, a2.x); fma2(accG3, wg.x, a3.x);                             \
    fma2(accO0, wo.x, a0.x); fma2(accO1, wo.x, a1.x);                             \
    fma2(accO2, wo.x, a2.x); fma2(accO3, wo.x, a3.x);                             \
    fma2(accI0, wi.y, a0.y); fma2(accI1, wi.y, a1.y);                             \
    fma2(accI2, wi.y, a2.y); fma2(accI3, wi.y, a3.y);                             \
    fma2(accF0, wf.y, a0.y); fma2(accF1, wf.y, a1.y);                             \
    fma2(accF2, wf.y, a2.y); fma2(accF3, wf.y, a3.y);                             \
    fma2(accG0, wg.y, a0.y); fma2(accG1, wg.y, a1.y);                             \
    fma2(accG2, wg.y, a2.y); fma2(accG3, wg.y, a3.y);                             \
    fma2(accO0, wo.y, a0.y); fma2(accO1, wo.y, a1.y);                             \
    fma2(accO2, wo.y, a2.y); fma2(accO3, wo.y, a3.y);                             \
} while (0)

    for (int t = 0; t < 512; t++) {
        float4* cur4 = (t & 1) ? actG1 : actG0;
        float4* nxt4 = (t & 1) ? actG0 : actG1;
        const float4* A4 = cur4 + b0;

        ull accI0=bI,accI1=bI,accI2=bI,accI3=bI;
        ull accF0=bF,accF1=bF,accF2=bF,accF3=bF;
        ull accG0=bG,accG1=bG,accG2=bG,accG3=bG;
        ull accO0=bO,accO1=bO,accO2=bO,accO3=bO;

        // software-pipelined k-pair loop (42 pairs)
        ulonglong2 wiA,wfA,wgA,woA,a0A,a1A,a2A,a3A;
        ulonglong2 wiB,wfB,wgB,woB,a0B,a1B,a2B,a3B;
        LOADP(wiA,wfA,wgA,woA,a0A,a1A,a2A,a3A, 0);
        #pragma unroll 5
        for (int kk = 0; kk < 40; kk += 2) {
            LOADP(wiB,wfB,wgB,woB,a0B,a1B,a2B,a3B, kk + 1);
            COMPP(wiA,wfA,wgA,woA,a0A,a1A,a2A,a3A);
            LOADP(wiA,wfA,wgA,woA,a0A,a1A,a2A,a3A, kk + 2);
            COMPP(wiB,wfB,wgB,woB,a0B,a1B,a2B,a3B);
        }
        LOADP(wiB,wfB,wgB,woB,a0B,a1B,a2B,a3B, 41);
        COMPP(wiA,wfA,wgA,woA,a0A,a1A,a2A,a3A);
        COMPP(wiB,wfB,wgB,woB,a0B,a1B,a2B,a3B);

        // fused pointwise (lane-private; cell state in registers)
        float2 vi, vf, vg, vo;
        float h0x,h0y,h1x,h1y,h2x,h2y,h3x,h3y;
        vi=upk(accI0); vf=upk(accF0); vg=upk(accG0); vo=upk(accO0);
        c0x = fmaf(sigf(vf.x), c0x, sigf(vi.x) * tanh_(vg.x));
        h0x = sigf(vo.x) * tanh_(c0x);
        c0y = fmaf(sigf(vf.y), c0y, sigf(vi.y) * tanh_(vg.y));
        h0y = sigf(vo.y) * tanh_(c0y);
        vi=upk(accI1); vf=upk(accF1); vg=upk(accG1); vo=upk(accO1);
        c1x = fmaf(sigf(vf.x), c1x, sigf(vi.x) * tanh_(vg.x));
        h1x = sigf(vo.x) * tanh_(c1x);
        c1y = fmaf(sigf(vf.y), c1y, sigf(vi.y) * tanh_(vg.y));
        h1y = sigf(vo.y) * tanh_(c1y);
        vi=upk(accI2); vf=upk(accF2); vg=upk(accG2); vo=upk(accO2);
        c2x = fmaf(sigf(vf.x), c2x, sigf(vi.x) * tanh_(vg.x));
        h2x = sigf(vo.x) * tanh_(c2x);
        c2y = fmaf(sigf(vf.y), c2y, sigf(vi.y) * tanh_(vg.y));
        h2y = sigf(vo.y) * tanh_(c2y);
        vi=upk(accI3); vf=upk(accF3); vg=upk(accG3); vo=upk(accO3);
        c3x = fmaf(sigf(vf.x), c3x, sigf(vi.x) * tanh_(vg.x));
        h3x = sigf(vo.x) * tanh_(c3x);
        c3y = fmaf(sigf(vf.y), c3y, sigf(vi.y) * tanh_(vg.y));
        h3y = sigf(vo.y) * tanh_(c3y);

        // h stores into paired-k layout: one STS.128 per batch (4 total)
        {
            float4* N4 = nxt4 + kkh * A2ROW + b0;
            N4[0] = make_float4(h0x, h0x, h0y, h0y);
            N4[1] = make_float4(h1x, h1x, h1y, h1y);
            N4[2] = make_float4(h2x, h2x, h2y, h2y);
            N4[3] = make_float4(h3x, h3x, h3y, h3y);
        }

        // per-warp embedding for t+1 (token prefetched a full step ahead)
        if (t < 511) {
            float* nxtf = reinterpret_cast<float*>(nxt4);
            #pragma unroll
            for (int b = 0; b < 4; b++) {
                float tx = __shfl_sync(0xffffffffu, tok_nxt.x, b);
                float ty = __shfl_sync(0xffffffffu, tok_nxt.y, b);
                if (l < 20) {
                    float v = fmaxf(fmaf(tx, eW[2 * l], ty * eW[2 * l + 1]), 0.0f);
                    *reinterpret_cast<float2*>(nxtf + (l >> 1) * (A2ROW * 4) +
                                               (eb0 + b) * 4 + (l & 1) * 2) =
                        make_float2(v, v);
                }
            }
            if (l < 4 && t < 510) tok_nxt = xrow[t + 2];
        }
        // group-local barrier — the two 4-warp groups run decoupled
        asm volatile("bar.sync %0, 128;" :: "r"(barid) : "memory");
    }

    // final h (after step 512) lives in buffer 0 (t=511 odd -> nxt = actG0)
    {
        const float* a0f = reinterpret_cast<const float*>(actG0);
        int tig = tid & 127;                 // thread index within group
        for (int idx = tig; idx < 1024; idx += 128) {
            int bb = idx >> 6, j = idx & 63;
            g_h64[(size_t)(bt * 32 + grp * 16 + bb) * 64 + j] =
                a0f[((20 + j) >> 1) * (A2ROW * 4) + bb * 4 + (j & 1) * 2];
        }
    }
#undef LOADP
#undef COMPP
}

// ---------------- LSTM2: single step, zero state -> f gate & Whh2 unused ----------------
__global__ void __launch_bounds__(256, 1)
lstm2_kernel(const float* __restrict__ Wih2, const float* __restrict__ b2)
{
    extern __shared__ float sm[];
    float* Ws   = sm;            // [type][k][j], type 0:i 1:g 2:o
    float* hact = sm + 49152;    // [k][b]
    const int tid = threadIdx.x;
    const int bt  = blockIdx.x;

    for (int idx = tid; idx < 3 * 64 * 256; idx += 256) {
        int tt = idx >> 14;
        int r  = idx & 16383;
        int k  = r >> 8, j = r & 255;
        int o  = (tt == 0) ? 0 : (tt == 1) ? 512 : 768;  // i, g, o offsets
        Ws[idx] = __ldg(&Wih2[(size_t)(o + j) * 64 + k]);
    }
    for (int idx = tid; idx < 2048; idx += 256) {
        int bb = idx >> 6, k = idx & 63;
        hact[k * 32 + bb] = g_h64[(size_t)(bt * 32 + bb) * 64 + k];
    }
    __syncthreads();

    const int w = tid >> 5, l = tid & 31;
    for (int jc = 0; jc < 4; jc++) {
        int j = jc * 64 + 2 * l;
        ull bI = pk(__ldg(&b2[j]),       __ldg(&b2[j + 1]));
        ull bG = pk(__ldg(&b2[512 + j]), __ldg(&b2[512 + j + 1]));
        ull bO = pk(__ldg(&b2[768 + j]), __ldg(&b2[768 + j + 1]));
        ull aI[4], aG[4], aO[4];
        #pragma unroll
        for (int q = 0; q < 4; q++) { aI[q] = bI; aG[q] = bG; aO[q] = bO; }

        #pragma unroll 4
        for (int k = 0; k < 64; k++) {
            float4 a = *reinterpret_cast<const float4*>(hact + k * 32 + 4 * w);
            ull a0 = pk(a.x, a.x), a1 = pk(a.y, a.y);
            ull a2 = pk(a.z, a.z), a3 = pk(a.w, a.w);
            float2 wi = *reinterpret_cast<const float2*>(Ws + k * 256 + j);
            float2 wg = *reinterpret_cast<const float2*>(Ws + 16384 + k * 256 + j);
            float2 wo = *reinterpret_cast<const float2*>(Ws + 32768 + k * 256 + j);
            ull wpi = pk(wi.x, wi.y), wpg = pk(wg.x, wg.y), wpo = pk(wo.x, wo.y);
            fma2(aI[0], wpi, a0); fma2(aI[1], wpi, a1);
            fma2(aI[2], wpi, a2); fma2(aI[3], wpi, a3);
            fma2(aG[0], wpg, a0); fma2(aG[1], wpg, a1);
            fma2(aG[2], wpg, a2); fma2(aG[3], wpg, a3);
            fma2(aO[0], wpo, a0); fma2(aO[1], wpo, a1);
            fma2(aO[2], wpo, a2); fma2(aO[3], wpo, a3);
        }
        #pragma unroll
        for (int q = 0; q < 4; q++) {
            float2 vi = upk(aI[q]);
            float2 vg = upk(aG[q]);
            float2 vo = upk(aO[q]);
            float c0 = sigf(vi.x) * tanh_(vg.x);
            float h0 = sigf(vo.x) * tanh_(c0);
            float c1 = sigf(vi.y) * tanh_(vg.y);
            float h1 = sigf(vo.y) * tanh_(c1);
            int bb = bt * 32 + 4 * w + q;
            *reinterpret_cast<float2*>(&g_h256[(size_t)bb * 256 + j]) =
                make_float2(h0, h1);
        }
    }
}

// ---------------- output projection: out = h256 @ Wout^T + bout ----------------
__global__ void __launch_bounds__(256)
out_kernel(const float* __restrict__ Wout, const float* __restrict__ bout,
           float* __restrict__ out)
{
    int gw = (blockIdx.x * 256 + threadIdx.x) >> 5;   // one warp per batch elem
    int l  = threadIdx.x & 31;
    if (gw >= 4096) return;
    const float* hrow = g_h256 + (size_t)gw * 256;
    float p0 = 0.0f, p1 = 0.0f;
    #pragma unroll
    for (int m = 0; m < 8; m++) {
        int j = l + 32 * m;
        float h = hrow[j];
        p0 = fmaf(h, __ldg(&Wout[j]), p0);
        p1 = fmaf(h, __ldg(&Wout[256 + j]), p1);
    }
    #pragma unroll
    for (int s = 16; s > 0; s >>= 1) {
        p0 += __shfl_xor_sync(0xffffffffu, p0, s);
        p1 += __shfl_xor_sync(0xffffffffu, p1, s);
    }
    if (l == 0) {
        out[gw * 2]     = p0 + __ldg(&bout[0]);
        out[gw * 2 + 1] = p1 + __ldg(&bout[1]);
    }
}

// ---------------- launch ----------------
extern "C" void kernel_launch(void* const* d_in, const int* in_sizes, int n_in,
                              void* d_out, int out_size)
{
    const float *x = nullptr, *W_embed = nullptr, *Wih1 = nullptr, *Whh1 = nullptr,
                *b1 = nullptr, *Wih2 = nullptr, *b2 = nullptr,
                *Wout = nullptr, *bout = nullptr;
    for (int i = 0; i < n_in; i++) {
        const float* p = (const float*)d_in[i];
        switch (in_sizes[i]) {
            case 4194304: x = p; break;        // (4096, 1024)
            case 40:      W_embed = p; break;  // (20, 2)
            case 5120:    Wih1 = p; break;     // (256, 20)
            case 16384:   Whh1 = p; break;     // (256, 64)
            case 256:     b1 = p; break;       // (256,)
            case 65536:   Wih2 = p; break;     // (1024, 64)
            case 262144:  /* Whh2 unused */ break;
            case 1024:    b2 = p; break;       // (1024,)
            case 512:     Wout = p; break;     // (2, 256)
            case 2:       bout = p; break;     // (2,)
            default: break;
        }
    }
    float* out = (float*)d_out;

    const int SMEM1 = S_TOT * 4;              // 132992 B
    const int SMEM2 = (49152 + 2048) * 4;     // 204800 B
    cudaFuncSetAttribute(lstm1_kernel, cudaFuncAttributeMaxDynamicSharedMemorySize, SMEM1);
    cudaFuncSetAttribute(lstm2_kernel, cudaFuncAttributeMaxDynamicSharedMemorySize, SMEM2);

    lstm1_kernel<<<128, 256, SMEM1>>>(x, W_embed, Wih1, Whh1, b1);
    lstm2_kernel<<<128, 256, SMEM2>>>(Wih2, b2);
    out_kernel<<<512, 256>>>(Wout, bout, out);
    (void)out_size;
}

// round 12
// speedup vs baseline: 1.0485x; 1.0485x over previous
#include <cuda_runtime.h>
#include <cstddef>

typedef unsigned long long ull;

// ---------------- scratch (static device globals; no allocation) ----------------
__device__ float g_h64[4096 * 64];     // LSTM1 final hidden
__device__ float g_h256[4096 * 256];   // LSTM2 hidden

// ---------------- packed f32x2 helpers ----------------
__device__ __forceinline__ ull pk(float lo, float hi) {
    ull r;
    asm("mov.b64 %0, {%1, %2};" : "=l"(r) : "f"(lo), "f"(hi));
    return r;
}
__device__ __forceinline__ void fma2(ull& d, ull a, ull b) {
    asm("fma.rn.f32x2 %0, %1, %2, %0;" : "+l"(d) : "l"(a), "l"(b));
}
__device__ __forceinline__ float2 upk(ull v) {
    float2 r;
    asm("mov.b64 {%0, %1}, %2;" : "=f"(r.x), "=f"(r.y) : "l"(v));
    return r;
}

// accurate activations for LSTM2 path (expf ~2ulp)
__device__ __forceinline__ float sigf(float x) {
    return __fdividef(1.0f, 1.0f + __expf(-x));
}
__device__ __forceinline__ float tanh_(float x) {
    return __fdividef(2.0f, 1.0f + __expf(-2.0f * x)) - 1.0f;
}

// 7-MUFU LSTM cell (algebraically identical to sigmoid/tanh form):
//   c' = [c*(1+ei)(1+eg) + (1-eg)(1+ef)] / [(1+ef)(1+ei)(1+eg)]
//   h  = (1-ec) / [(1+eo)(1+ec)],  ec = exp(-2c')
__device__ __forceinline__ float lstm_cell(float i_, float f_, float g_, float o_,
                                           float& c) {
    float ef = __expf(-f_);
    float ei = __expf(-i_);
    float eg = __expf(-2.0f * g_);
    float p  = (1.0f + ei) * (1.0f + eg);
    float num = fmaf(c, p, (1.0f - eg) * (1.0f + ef));
    float den = (1.0f + ef) * p;
    c = __fdividef(num, den);
    float eo = __expf(-o_);
    float ec = __expf(-2.0f * c);
    return __fdividef(1.0f - ec, (1.0f + eo) * (1.0f + ec));
}

// ---------------- shared layout for LSTM1 (float offsets) ----------------
// Wq   float4[42][128]            : 21504 floats (k-pair packed weights)
// ACT  float4[4 grp][2 buf][42][9]: 8*378 float4 = 12096 floats
//      (act, k-pair packed + dup: {a[2k][b],a[2k][b],a[2k+1][b],a[2k+1][b]}, 8 batches + pad)
// bsh [256], eW [64]
#define S_WQ    0
#define S_ACT   21504
#define S_BSH   (S_ACT + 12096)      // 33600
#define S_EW    (S_BSH + 256)        // 33856
#define S_TOT   (S_EW + 64)          // 33920 floats = 135680 B
#define A2ROW   9                     // float4 per row (8 batches + 1 pad)
#define ABUF    378                   // float4 per buffer (42 * 9)

__global__ void __launch_bounds__(256, 1)
lstm1_kernel(const float* __restrict__ x,
             const float* __restrict__ W_embed,
             const float* __restrict__ Wih1,
             const float* __restrict__ Whh1,
             const float* __restrict__ b1)
{
    extern __shared__ float sm[];
    float4* Wq4  = reinterpret_cast<float4*>(sm + S_WQ);
    float4* ACT4 = reinterpret_cast<float4*>(sm + S_ACT);
    float*  bsh  = sm + S_BSH;
    float*  eW   = sm + S_EW;

    const int tid = threadIdx.x;
    const int bt  = blockIdx.x;          // batch tile (32 elems)

    // combined paired-k weight (gate order i|f|g|o)
    for (int idx = tid; idx < 42 * 128; idx += 256) {
        int kk = idx >> 7, pj = idx & 127;
        int g0 = 2 * pj;
        int k0 = 2 * kk, k1 = k0 + 1;
        float4 v;
        v.x = (k0 < 20) ? __ldg(&Wih1[g0 * 20 + k0])     : __ldg(&Whh1[g0 * 64 + (k0 - 20)]);
        v.y = (k0 < 20) ? __ldg(&Wih1[(g0+1) * 20 + k0]) : __ldg(&Whh1[(g0+1) * 64 + (k0 - 20)]);
        v.z = (k1 < 20) ? __ldg(&Wih1[g0 * 20 + k1])     : __ldg(&Whh1[g0 * 64 + (k1 - 20)]);
        v.w = (k1 < 20) ? __ldg(&Wih1[(g0+1) * 20 + k1]) : __ldg(&Whh1[(g0+1) * 64 + (k1 - 20)]);
        Wq4[idx] = v;
    }
    bsh[tid] = b1[tid];
    if (tid < 40) eW[tid] = W_embed[tid];
    // zero all act buffers (covers h rows of every group's buffer 0)
    for (int idx = tid; idx < 8 * ABUF; idx += 256)
        ACT4[idx] = make_float4(0.f, 0.f, 0.f, 0.f);
    __syncthreads();

    // ---- mapping ----
    // warp w: group grp = w>>1 (8 batches each), wl = w&1 -> j-half (32 j's)
    // lane: j0 = wl*32 + 2*(l&15) gate pair; b0 = 4*(l>>4) batch quad (of 8)
    // SMSP w%4 hosts warps from two DIFFERENT groups (w, w+4) -> decoupled phases.
    const int w   = tid >> 5, l = tid & 31;
    const int grp = w >> 1,  wl = w & 1;
    const int j0  = wl * 32 + 2 * (l & 15);  // gate index pair within 64-wide type
    const int b0  = 4 * (l >> 4);            // batch quad (within group's 8)
    const int barid = 1 + grp;

    float4* actG0 = ACT4 + (grp * 2) * ABUF;       // buffer parity 0
    float4* actG1 = actG0 + ABUF;                  // buffer parity 1

    const float4* W4I = Wq4 + (wl * 16 + (l & 15));  // pj for type i
    const float4* W4F = W4I + 32;
    const float4* W4G = W4I + 64;
    const float4* W4O = W4I + 96;

    const ull bI = pk(bsh[j0],       bsh[j0 + 1]);
    const ull bF = pk(bsh[64 + j0],  bsh[64 + j0 + 1]);
    const ull bG = pk(bsh[128 + j0], bsh[128 + j0 + 1]);
    const ull bO = pk(bsh[192 + j0], bsh[192 + j0 + 1]);

    const int kkh = 10 + (j0 >> 1);      // h-row pair index for (j0, j0+1)

    // register-resident cell state
    float c0x=0.f,c0y=0.f,c1x=0.f,c1y=0.f,c2x=0.f,c2y=0.f,c3x=0.f,c3y=0.f;

    // embedding duty: warp wl owns group-local batches wl*4 .. wl*4+3
    const int eb0 = wl * 4;
    const float2* xrow = reinterpret_cast<const float2*>(x) +
                         (size_t)(bt * 32 + grp * 8 + eb0 + l) * 512;  // deref only l<4
    float2 tok = make_float2(0.f, 0.f), tok_nxt = make_float2(0.f, 0.f);
    if (l < 4) tok = xrow[0];
    // initial embedding (t=0) into group buffer 0
    {
        float* a0f = reinterpret_cast<float*>(actG0);
        #pragma unroll
        for (int b = 0; b < 4; b++) {
            float tx = __shfl_sync(0xffffffffu, tok.x, b);
            float ty = __shfl_sync(0xffffffffu, tok.y, b);
            if (l < 20) {
                float v = fmaxf(fmaf(tx, eW[2 * l], ty * eW[2 * l + 1]), 0.0f);
                *reinterpret_cast<float2*>(a0f + (l >> 1) * (A2ROW * 4) +
                                           (eb0 + b) * 4 + (l & 1) * 2) = make_float2(v, v);
            }
        }
    }
    if (l < 4) tok_nxt = xrow[1];
    asm volatile("bar.sync %0, 64;" :: "r"(barid) : "memory");

#define LOADP(wi,wf,wg,wo,a0,a1,a2,a3, kk) do {                                   \
    wi = *reinterpret_cast<const ulonglong2*>(W4I + (kk) * 128);                  \
    wf = *reinterpret_cast<const ulonglong2*>(W4F + (kk) * 128);                  \
    wg = *reinterpret_cast<const ulonglong2*>(W4G + (kk) * 128);                  \
    wo = *reinterpret_cast<const ulonglong2*>(W4O + (kk) * 128);                  \
    a0 = *reinterpret_cast<const ulonglong2*>(A4 + (kk) * A2ROW);                 \
    a1 = *reinterpret_cast<const ulonglong2*>(A4 + (kk) * A2ROW + 1);             \
    a2 = *reinterpret_cast<const ulonglong2*>(A4 + (kk) * A2ROW + 2);             \
    a3 = *reinterpret_cast<const ulonglong2*>(A4 + (kk) * A2ROW + 3);             \
} while (0)

#define COMPP(wi,wf,wg,wo,a0,a1,a2,a3) do {                                       \
    fma2(accI0, wi.x, a0.x); fma2(accI1, wi.x, a1.x);                             \
    fma2(accI2, wi.x, a2.x); fma2(accI3, wi.x, a3.x);                             \
    fma2(accF0, wf.x, a0.x); fma2(accF1, wf.x, a1.x);                             \
    fma2(accF2, wf.x, a2.x); fma2(accF3, wf.x, a3.x);                             \
    fma2(accG0, wg.x, a0.x); fma2(accG1, wg.x, a1.x);                             \
    fma2(accG2, wg.x, a2.x); fma2(accG3, wg.x, a3.x);                             \
    fma2(accO0, wo.x, a0.x); fma2(accO1, wo.x, a1.x);                             \
    fma2(accO2, wo.x, a2.x); fma2(accO3, wo.x, a3.x);                             \
    fma2(accI0, wi.y, a0.y); fma2(accI1, wi.y, a1.y);                             \
    fma2(accI2, wi.y, a2.y); fma2(accI3, wi.y, a3.y);                             \
    fma2(accF0, wf.y, a0.y); fma2(accF1, wf.y, a1.y);                             \
    fma2(accF2, wf.y, a2.y); fma2(accF3, wf.y, a3.y);                             \
    fma2(accG0, wg.y, a0.y); fma2(accG1, wg.y, a1.y);                             \
    fma2(accG2, wg.y, a2.y); fma2(accG3, wg.y, a3.y);                             \
    fma2(accO0, wo.y, a0.y); fma2(accO1, wo.y, a1.y);                             \
    fma2(accO2, wo.y, a2.y); fma2(accO3, wo.y, a3.y);                             \
} while (0)

    for (int t = 0; t < 512; t++) {
        float4* cur4 = (t & 1) ? actG1 : actG0;
        float4* nxt4 = (t & 1) ? actG0 : actG1;
        const float4* A4 = cur4 + b0;

        ull accI0=bI,accI1=bI,accI2=bI,accI3=bI;
        ull accF0=bF,accF1=bF,accF2=bF,accF3=bF;
        ull accG0=bG,accG1=bG,accG2=bG,accG3=bG;
        ull accO0=bO,accO1=bO,accO2=bO,accO3=bO;

        // software-pipelined k-pair loop (42 pairs)
        ulonglong2 wiA,wfA,wgA,woA,a0A,a1A,a2A,a3A;
        ulonglong2 wiB,wfB,wgB,woB,a0B,a1B,a2B,a3B;
        LOADP(wiA,wfA,wgA,woA,a0A,a1A,a2A,a3A, 0);
        #pragma unroll 5
        for (int kk = 0; kk < 40; kk += 2) {
            LOADP(wiB,wfB,wgB,woB,a0B,a1B,a2B,a3B, kk + 1);
            COMPP(wiA,wfA,wgA,woA,a0A,a1A,a2A,a3A);
            LOADP(wiA,wfA,wgA,woA,a0A,a1A,a2A,a3A, kk + 2);
            COMPP(wiB,wfB,wgB,woB,a0B,a1B,a2B,a3B);
        }
        LOADP(wiB,wfB,wgB,woB,a0B,a1B,a2B,a3B, 41);
        COMPP(wiA,wfA,wgA,woA,a0A,a1A,a2A,a3A);
        COMPP(wiB,wfB,wgB,woB,a0B,a1B,a2B,a3B);

        // fused pointwise (7-MUFU cell; cell state in registers)
        float2 vi, vf, vg, vo;
        float h0x,h0y,h1x,h1y,h2x,h2y,h3x,h3y;
        vi=upk(accI0); vf=upk(accF0); vg=upk(accG0); vo=upk(accO0);
        h0x = lstm_cell(vi.x, vf.x, vg.x, vo.x, c0x);
        h0y = lstm_cell(vi.y, vf.y, vg.y, vo.y, c0y);
        vi=upk(accI1); vf=upk(accF1); vg=upk(accG1); vo=upk(accO1);
        h1x = lstm_cell(vi.x, vf.x, vg.x, vo.x, c1x);
        h1y = lstm_cell(vi.y, vf.y, vg.y, vo.y, c1y);
        vi=upk(accI2); vf=upk(accF2); vg=upk(accG2); vo=upk(accO2);
        h2x = lstm_cell(vi.x, vf.x, vg.x, vo.x, c2x);
        h2y = lstm_cell(vi.y, vf.y, vg.y, vo.y, c2y);
        vi=upk(accI3); vf=upk(accF3); vg=upk(accG3); vo=upk(accO3);
        h3x = lstm_cell(vi.x, vf.x, vg.x, vo.x, c3x);
        h3y = lstm_cell(vi.y, vf.y, vg.y, vo.y, c3y);

        // h stores into paired-k layout: one STS.128 per batch (4 total)
        {
            float4* N4 = nxt4 + kkh * A2ROW + b0;
            N4[0] = make_float4(h0x, h0x, h0y, h0y);
            N4[1] = make_float4(h1x, h1x, h1y, h1y);
            N4[2] = make_float4(h2x, h2x, h2y, h2y);
            N4[3] = make_float4(h3x, h3x, h3y, h3y);
        }

        // per-warp embedding for t+1 (token prefetched a full step ahead)
        if (t < 511) {
            float* nxtf = reinterpret_cast<float*>(nxt4);
            #pragma unroll
            for (int b = 0; b < 4; b++) {
                float tx = __shfl_sync(0xffffffffu, tok_nxt.x, b);
                float ty = __shfl_sync(0xffffffffu, tok_nxt.y, b);
                if (l < 20) {
                    float v = fmaxf(fmaf(tx, eW[2 * l], ty * eW[2 * l + 1]), 0.0f);
                    *reinterpret_cast<float2*>(nxtf + (l >> 1) * (A2ROW * 4) +
                                               (eb0 + b) * 4 + (l & 1) * 2) =
                        make_float2(v, v);
                }
            }
            if (l < 4 && t < 510) tok_nxt = xrow[t + 2];
        }
        // group-local 2-warp barrier — four groups run fully decoupled
        asm volatile("bar.sync %0, 64;" :: "r"(barid) : "memory");
    }

    // final h (after step 512) lives in buffer 0 (t=511 odd -> nxt = actG0)
    {
        const float* a0f = reinterpret_cast<const float*>(actG0);
        int tig = tid & 63;                  // thread index within group (2 warps)
        for (int idx = tig; idx < 512; idx += 64) {
            int bb = idx >> 6, j = idx & 63;
            g_h64[(size_t)(bt * 32 + grp * 8 + bb) * 64 + j] =
                a0f[((20 + j) >> 1) * (A2ROW * 4) + bb * 4 + (j & 1) * 2];
        }
    }
#undef LOADP
#undef COMPP
}

// ---------------- LSTM2: single step, zero state -> f gate & Whh2 unused ----------------
__global__ void __launch_bounds__(256, 1)
lstm2_kernel(const float* __restrict__ Wih2, const float* __restrict__ b2)
{
    extern __shared__ float sm[];
    float* Ws   = sm;            // [type][k][j], type 0:i 1:g 2:o
    float* hact = sm + 49152;    // [k][b]
    const int tid = threadIdx.x;
    const int bt  = blockIdx.x;

    for (int idx = tid; idx < 3 * 64 * 256; idx += 256) {
        int tt = idx >> 14;
        int r  = idx & 16383;
        int k  = r >> 8, j = r & 255;
        int o  = (tt == 0) ? 0 : (tt == 1) ? 512 : 768;  // i, g, o offsets
        Ws[idx] = __ldg(&Wih2[(size_t)(o + j) * 64 + k]);
    }
    for (int idx = tid; idx < 2048; idx += 256) {
        int bb = idx >> 6, k = idx & 63;
        hact[k * 32 + bb] = g_h64[(size_t)(bt * 32 + bb) * 64 + k];
    }
    __syncthreads();

    const int w = tid >> 5, l = tid & 31;
    for (int jc = 0; jc < 4; jc++) {
        int j = jc * 64 + 2 * l;
        ull bI = pk(__ldg(&b2[j]),       __ldg(&b2[j + 1]));
        ull bG = pk(__ldg(&b2[512 + j]), __ldg(&b2[512 + j + 1]));
        ull bO = pk(__ldg(&b2[768 + j]), __ldg(&b2[768 + j + 1]));
        ull aI[4], aG[4], aO[4];
        #pragma unroll
        for (int q = 0; q < 4; q++) { aI[q] = bI; aG[q] = bG; aO[q] = bO; }

        #pragma unroll 4
        for (int k = 0; k < 64; k++) {
            float4 a = *reinterpret_cast<const float4*>(hact + k * 32 + 4 * w);
            ull a0 = pk(a.x, a.x), a1 = pk(a.y, a.y);
            ull a2 = pk(a.z, a.z), a3 = pk(a.w, a.w);
            float2 wi = *reinterpret_cast<const float2*>(Ws + k * 256 + j);
            float2 wg = *reinterpret_cast<const float2*>(Ws + 16384 + k * 256 + j);
            float2 wo = *reinterpret_cast<const float2*>(Ws + 32768 + k * 256 + j);
            ull wpi = pk(wi.x, wi.y), wpg = pk(wg.x, wg.y), wpo = pk(wo.x, wo.y);
            fma2(aI[0], wpi, a0); fma2(aI[1], wpi, a1);
            fma2(aI[2], wpi, a2); fma2(aI[3], wpi, a3);
            fma2(aG[0], wpg, a0); fma2(aG[1], wpg, a1);
            fma2(aG[2], wpg, a2); fma2(aG[3], wpg, a3);
            fma2(aO[0], wpo, a0); fma2(aO[1], wpo, a1);
            fma2(aO[2], wpo, a2); fma2(aO[3], wpo, a3);
        }
        #pragma unroll
        for (int q = 0; q < 4; q++) {
            float2 vi = upk(aI[q]);
            float2 vg = upk(aG[q]);
            float2 vo = upk(aO[q]);
            float c0 = sigf(vi.x) * tanh_(vg.x);
            float h0 = sigf(vo.x) * tanh_(c0);
            float c1 = sigf(vi.y) * tanh_(vg.y);
            float h1 = sigf(vo.y) * tanh_(c1);
            int bb = bt * 32 + 4 * w + q;
            *reinterpret_cast<float2*>(&g_h256[(size_t)bb * 256 + j]) =
                make_float2(h0, h1);
        }
    }
}

// ---------------- output projection: out = h256 @ Wout^T + bout ----------------
__global__ void __launch_bounds__(256)
out_kernel(const float* __restrict__ Wout, const float* __restrict__ bout,
           float* __restrict__ out)
{
    int gw = (blockIdx.x * 256 + threadIdx.x) >> 5;   // one warp per batch elem
    int l  = threadIdx.x & 31;
    if (gw >= 4096) return;
    const float* hrow = g_h256 + (size_t)gw * 256;
    float p0 = 0.0f, p1 = 0.0f;
    #pragma unroll
    for (int m = 0; m < 8; m++) {
        int j = l + 32 * m;
        float h = hrow[j];
        p0 = fmaf(h, __ldg(&Wout[j]), p0);
        p1 = fmaf(h, __ldg(&Wout[256 + j]), p1);
    }
    #pragma unroll
    for (int s = 16; s > 0; s >>= 1) {
        p0 += __shfl_xor_sync(0xffffffffu, p0, s);
        p1 += __shfl_xor_sync(0xffffffffu, p1, s);
    }
    if (l == 0) {
        out[gw * 2]     = p0 + __ldg(&bout[0]);
        out[gw * 2 + 1] = p1 + __ldg(&bout[1]);
    }
}

// ---------------- launch ----------------
extern "C" void kernel_launch(void* const* d_in, const int* in_sizes, int n_in,
                              void* d_out, int out_size)
{
    const float *x = nullptr, *W_embed = nullptr, *Wih1 = nullptr, *Whh1 = nullptr,
                *b1 = nullptr, *Wih2 = nullptr, *b2 = nullptr,
                *Wout = nullptr, *bout = nullptr;
    for (int i = 0; i < n_in; i++) {
        const float* p = (const float*)d_in[i];
        switch (in_sizes[i]) {
            case 4194304: x = p; break;        // (4096, 1024)
            case 40:      W_embed = p; break;  // (20, 2)
            case 5120:    Wih1 = p; break;     // (256, 20)
            case 16384:   Whh1 = p; break;     // (256, 64)
            case 256:     b1 = p; break;       // (256,)
            case 65536:   Wih2 = p; break;     // (1024, 64)
            case 262144:  /* Whh2 unused */ break;
            case 1024:    b2 = p; break;       // (1024,)
            case 512:     Wout = p; break;     // (2, 256)
            case 2:       bout = p; break;     // (2,)
            default: break;
        }
    }
    float* out = (float*)d_out;

    const int SMEM1 = S_TOT * 4;              // 135680 B
    const int SMEM2 = (49152 + 2048) * 4;     // 204800 B
    cudaFuncSetAttribute(lstm1_kernel, cudaFuncAttributeMaxDynamicSharedMemorySize, SMEM1);
    cudaFuncSetAttribute(lstm2_kernel, cudaFuncAttributeMaxDynamicSharedMemorySize, SMEM2);

    lstm1_kernel<<<128, 256, SMEM1>>>(x, W_embed, Wih1, Whh1, b1);
    lstm2_kernel<<<128, 256, SMEM2>>>(Wih2, b2);
    out_kernel<<<512, 256>>>(Wout, bout, out);
    (void)out_size;
}

// round 13
// speedup vs baseline: 1.2058x; 1.1500x over previous
#include <cuda_runtime.h>
#include <cstddef>

typedef unsigned long long ull;

// ---------------- scratch (static device globals; no allocation) ----------------
__device__ float g_h64[4096 * 64];     // LSTM1 final hidden
__device__ float g_h256[4096 * 256];   // LSTM2 hidden

// ---------------- packed f32x2 helpers ----------------
__device__ __forceinline__ ull pk(float lo, float hi) {
    ull r;
    asm("mov.b64 %0, {%1, %2};" : "=l"(r) : "f"(lo), "f"(hi));
    return r;
}
__device__ __forceinline__ void fma2(ull& d, ull a, ull b) {
    asm("fma.rn.f32x2 %0, %1, %2, %0;" : "+l"(d) : "l"(a), "l"(b));
}
__device__ __forceinline__ float2 upk(ull v) {
    float2 r;
    asm("mov.b64 {%0, %1}, %2;" : "=f"(r.x), "=f"(r.y) : "l"(v));
    return r;
}

// accurate activations for LSTM2 path (expf ~2ulp)
__device__ __forceinline__ float sigf(float x) {
    return __fdividef(1.0f, 1.0f + __expf(-x));
}
__device__ __forceinline__ float tanh_(float x) {
    return __fdividef(2.0f, 1.0f + __expf(-2.0f * x)) - 1.0f;
}

// 7-MUFU LSTM cell (algebraically identical to sigmoid/tanh form)
__device__ __forceinline__ float lstm_cell(float i_, float f_, float g_, float o_,
                                           float& c) {
    float ef = __expf(-f_);
    float ei = __expf(-i_);
    float eg = __expf(-2.0f * g_);
    float p  = (1.0f + ei) * (1.0f + eg);
    float num = fmaf(c, p, (1.0f - eg) * (1.0f + ef));
    float den = (1.0f + ef) * p;
    c = __fdividef(num, den);
    float eo = __expf(-o_);
    float ec = __expf(-2.0f * c);
    return __fdividef(1.0f - ec, (1.0f + eo) * (1.0f + ec));
}

// ---------------- shared layout for LSTM1 (float offsets) ----------------
// Wq   float4[42][128]            : 21504 floats (k-pair packed weights)
// ACT  float4[4 grp][2 buf][42][5]: 8*210 float4 = 6720 floats, NON-duplicated
//      row kk: slot = parity*2 + bq -> float4 a[2kk+parity][4*bq .. 4*bq+3]; slot 4 = pad
// bsh [256], eW [64]
#define S_WQ    0
#define S_ACT   21504
#define S_BSH   (S_ACT + 6720)       // 28224
#define S_EW    (S_BSH + 256)        // 28480
#define S_TOT   (S_EW + 64)          // 28544 floats = 114176 B
#define AKROW   5                     // float4 per kk row (4 slots + 1 pad)
#define ABUF    210                   // float4 per buffer (42 * 5)

__global__ void __launch_bounds__(256, 1)
lstm1_kernel(const float* __restrict__ x,
             const float* __restrict__ W_embed,
             const float* __restrict__ Wih1,
             const float* __restrict__ Whh1,
             const float* __restrict__ b1)
{
    extern __shared__ float sm[];
    float4* Wq4  = reinterpret_cast<float4*>(sm + S_WQ);
    float4* ACT4 = reinterpret_cast<float4*>(sm + S_ACT);
    float*  bsh  = sm + S_BSH;
    float*  eW   = sm + S_EW;

    const int tid = threadIdx.x;
    const int bt  = blockIdx.x;          // batch tile (32 elems)

    // combined paired-k weight (gate order i|f|g|o)
    for (int idx = tid; idx < 42 * 128; idx += 256) {
        int kk = idx >> 7, pj = idx & 127;
        int g0 = 2 * pj;
        int k0 = 2 * kk, k1 = k0 + 1;
        float4 v;
        v.x = (k0 < 20) ? __ldg(&Wih1[g0 * 20 + k0])     : __ldg(&Whh1[g0 * 64 + (k0 - 20)]);
        v.y = (k0 < 20) ? __ldg(&Wih1[(g0+1) * 20 + k0]) : __ldg(&Whh1[(g0+1) * 64 + (k0 - 20)]);
        v.z = (k1 < 20) ? __ldg(&Wih1[g0 * 20 + k1])     : __ldg(&Whh1[g0 * 64 + (k1 - 20)]);
        v.w = (k1 < 20) ? __ldg(&Wih1[(g0+1) * 20 + k1]) : __ldg(&Whh1[(g0+1) * 64 + (k1 - 20)]);
        Wq4[idx] = v;
    }
    bsh[tid] = b1[tid];
    if (tid < 40) eW[tid] = W_embed[tid];
    // zero all act buffers
    for (int idx = tid; idx < 8 * ABUF; idx += 256)
        ACT4[idx] = make_float4(0.f, 0.f, 0.f, 0.f);
    __syncthreads();

    // ---- mapping ----
    // warp w: group grp = w>>1 (8 batches), wl = w&1 -> j-half (32 j's)
    // lane: j0 = wl*32 + 2*(l&15) gate pair; b0 = 4*(l>>4) batch quad; bq = l>>4
    const int w   = tid >> 5, l = tid & 31;
    const int grp = w >> 1,  wl = w & 1;
    const int j0  = wl * 32 + 2 * (l & 15);
    const int bq  = l >> 4;
    const int barid = 1 + grp;

    float4* actG0 = ACT4 + (grp * 2) * ABUF;       // buffer parity 0
    float4* actG1 = actG0 + ABUF;                  // buffer parity 1

    const float4* W4I = Wq4 + (wl * 16 + (l & 15));  // pj for type i
    const float4* W4F = W4I + 32;
    const float4* W4G = W4I + 64;
    const float4* W4O = W4I + 96;

    const ull bI = pk(bsh[j0],       bsh[j0 + 1]);
    const ull bF = pk(bsh[64 + j0],  bsh[64 + j0 + 1]);
    const ull bG = pk(bsh[128 + j0], bsh[128 + j0 + 1]);
    const ull bO = pk(bsh[192 + j0], bsh[192 + j0 + 1]);

    const int kkh = 10 + (j0 >> 1);      // h-row pair index for (j0, j0+1); 20+j0 even

    // register-resident cell state: c[b 0..3][j parity]
    float c0x=0.f,c0y=0.f,c1x=0.f,c1y=0.f,c2x=0.f,c2y=0.f,c3x=0.f,c3y=0.f;

    // embedding duty: warp wl owns group-local batches wl*4 .. wl*4+3
    const int eb0 = wl * 4;
    const float2* xrow = reinterpret_cast<const float2*>(x) +
                         (size_t)(bt * 32 + grp * 8 + eb0 + l) * 512;  // deref only l<4
    float2 tok = make_float2(0.f, 0.f), tok_nxt = make_float2(0.f, 0.f);
    if (l < 4) tok = xrow[0];
    // initial embedding (t=0) into group buffer 0 (non-dup: scalar stores)
    {
        float* a0f = reinterpret_cast<float*>(actG0);
        #pragma unroll
        for (int b = 0; b < 4; b++) {
            float tx = __shfl_sync(0xffffffffu, tok.x, b);
            float ty = __shfl_sync(0xffffffffu, tok.y, b);
            if (l < 20) {
                float v = fmaxf(fmaf(tx, eW[2 * l], ty * eW[2 * l + 1]), 0.0f);
                int bb = eb0 + b;
                a0f[(l >> 1) * (AKROW * 4) + (l & 1) * 8 + (bb >> 2) * 4 + (bb & 3)] = v;
            }
        }
    }
    if (l < 4) tok_nxt = xrow[1];
    asm volatile("bar.sync %0, 64;" :: "r"(barid) : "memory");

#define LOADP(wi,wf,wg,wo,aP,aQ, kk) do {                                         \
    wi = *reinterpret_cast<const ulonglong2*>(W4I + (kk) * 128);                  \
    wf = *reinterpret_cast<const ulonglong2*>(W4F + (kk) * 128);                  \
    wg = *reinterpret_cast<const ulonglong2*>(W4G + (kk) * 128);                  \
    wo = *reinterpret_cast<const ulonglong2*>(W4O + (kk) * 128);                  \
    aP = A4[(kk) * AKROW];            /* parity 0: a[2kk][b0..b3] */              \
    aQ = A4[(kk) * AKROW + 2];        /* parity 1: a[2kk+1][b0..b3] */            \
} while (0)

#define COMPP(wi,wf,wg,wo,aP,aQ) do {                                             \
    ull d0 = pk(aP.x, aP.x), d1 = pk(aP.y, aP.y);                                 \
    ull d2 = pk(aP.z, aP.z), d3 = pk(aP.w, aP.w);                                 \
    fma2(accI0, wi.x, d0); fma2(accI1, wi.x, d1);                                 \
    fma2(accI2, wi.x, d2); fma2(accI3, wi.x, d3);                                 \
    fma2(accF0, wf.x, d0); fma2(accF1, wf.x, d1);                                 \
    fma2(accF2, wf.x, d2); fma2(accF3, wf.x, d3);                                 \
    fma2(accG0, wg.x, d0); fma2(accG1, wg.x, d1);                                 \
    fma2(accG2, wg.x, d2); fma2(accG3, wg.x, d3);                                 \
    fma2(accO0, wo.x, d0); fma2(accO1, wo.x, d1);                                 \
    fma2(accO2, wo.x, d2); fma2(accO3, wo.x, d3);                                 \
    ull e0 = pk(aQ.x, aQ.x), e1 = pk(aQ.y, aQ.y);                                 \
    ull e2 = pk(aQ.z, aQ.z), e3 = pk(aQ.w, aQ.w);                                 \
    fma2(accI0, wi.y, e0); fma2(accI1, wi.y, e1);                                 \
    fma2(accI2, wi.y, e2); fma2(accI3, wi.y, e3);                                 \
    fma2(accF0, wf.y, e0); fma2(accF1, wf.y, e1);                                 \
    fma2(accF2, wf.y, e2); fma2(accF3, wf.y, e3);                                 \
    fma2(accG0, wg.y, e0); fma2(accG1, wg.y, e1);                                 \
    fma2(accG2, wg.y, e2); fma2(accG3, wg.y, e3);                                 \
    fma2(accO0, wo.y, e0); fma2(accO1, wo.y, e1);                                 \
    fma2(accO2, wo.y, e2); fma2(accO3, wo.y, e3);                                 \
} while (0)

    for (int t = 0; t < 512; t++) {
        float4* cur4 = (t & 1) ? actG1 : actG0;
        float4* nxt4 = (t & 1) ? actG0 : actG1;
        const float4* A4 = cur4 + bq;

        ull accI0=bI,accI1=bI,accI2=bI,accI3=bI;
        ull accF0=bF,accF1=bF,accF2=bF,accF3=bF;
        ull accG0=bG,accG1=bG,accG2=bG,accG3=bG;
        ull accO0=bO,accO1=bO,accO2=bO,accO3=bO;

        // software-pipelined k-pair loop (42 pairs)
        ulonglong2 wiA,wfA,wgA,woA; float4 aPA,aQA;
        ulonglong2 wiB,wfB,wgB,woB; float4 aPB,aQB;
        LOADP(wiA,wfA,wgA,woA,aPA,aQA, 0);
        #pragma unroll 5
        for (int kk = 0; kk < 40; kk += 2) {
            LOADP(wiB,wfB,wgB,woB,aPB,aQB, kk + 1);
            COMPP(wiA,wfA,wgA,woA,aPA,aQA);
            LOADP(wiA,wfA,wgA,woA,aPA,aQA, kk + 2);
            COMPP(wiB,wfB,wgB,woB,aPB,aQB);
        }
        LOADP(wiB,wfB,wgB,woB,aPB,aQB, 41);
        COMPP(wiA,wfA,wgA,woA,aPA,aQA);
        COMPP(wiB,wfB,wgB,woB,aPB,aQB);

        // fused pointwise (7-MUFU cell; cell state in registers)
        float2 vi, vf, vg, vo;
        float h0x,h0y,h1x,h1y,h2x,h2y,h3x,h3y;
        vi=upk(accI0); vf=upk(accF0); vg=upk(accG0); vo=upk(accO0);
        h0x = lstm_cell(vi.x, vf.x, vg.x, vo.x, c0x);
        h0y = lstm_cell(vi.y, vf.y, vg.y, vo.y, c0y);
        vi=upk(accI1); vf=upk(accF1); vg=upk(accG1); vo=upk(accO1);
        h1x = lstm_cell(vi.x, vf.x, vg.x, vo.x, c1x);
        h1y = lstm_cell(vi.y, vf.y, vg.y, vo.y, c1y);
        vi=upk(accI2); vf=upk(accF2); vg=upk(accG2); vo=upk(accO2);
        h2x = lstm_cell(vi.x, vf.x, vg.x, vo.x, c2x);
        h2y = lstm_cell(vi.y, vf.y, vg.y, vo.y, c2y);
        vi=upk(accI3); vf=upk(accF3); vg=upk(accG3); vo=upk(accO3);
        h3x = lstm_cell(vi.x, vf.x, vg.x, vo.x, c3x);
        h3y = lstm_cell(vi.y, vf.y, vg.y, vo.y, c3y);

        // h stores, non-dup layout: 2 STS.128 per lane
        // row kkh: slot bq (parity 0, j0) and slot 2+bq (parity 1, j0+1)
        {
            float4* N4 = nxt4 + kkh * AKROW + bq;
            N4[0] = make_float4(h0x, h1x, h2x, h3x);
            N4[2] = make_float4(h0y, h1y, h2y, h3y);
        }

        // per-warp embedding for t+1 (token prefetched a full step ahead)
        if (t < 511) {
            float* nxtf = reinterpret_cast<float*>(nxt4);
            #pragma unroll
            for (int b = 0; b < 4; b++) {
                float tx = __shfl_sync(0xffffffffu, tok_nxt.x, b);
                float ty = __shfl_sync(0xffffffffu, tok_nxt.y, b);
                if (l < 20) {
                    float v = fmaxf(fmaf(tx, eW[2 * l], ty * eW[2 * l + 1]), 0.0f);
                    int bb = eb0 + b;
                    nxtf[(l >> 1) * (AKROW * 4) + (l & 1) * 8 + (bb >> 2) * 4 + (bb & 3)] = v;
                }
            }
            if (l < 4 && t < 510) tok_nxt = xrow[t + 2];
        }
        // group-local 2-warp barrier — four groups run fully decoupled
        asm volatile("bar.sync %0, 64;" :: "r"(barid) : "memory");
    }

    // final h (after step 512) lives in buffer 0 (t=511 odd -> nxt = actG0)
    {
        const float* a0f = reinterpret_cast<const float*>(actG0);
        int tig = tid & 63;                  // thread index within group (2 warps)
        for (int idx = tig; idx < 512; idx += 64) {
            int bb = idx >> 6, j = idx & 63;
            g_h64[(size_t)(bt * 32 + grp * 8 + bb) * 64 + j] =
                a0f[((20 + j) >> 1) * (AKROW * 4) + ((20 + j) & 1) * 8 +
                    (bb >> 2) * 4 + (bb & 3)];
        }
    }
#undef LOADP
#undef COMPP
}

// ---------------- LSTM2: single step, zero state -> f gate & Whh2 unused ----------------
__global__ void __launch_bounds__(256, 1)
lstm2_kernel(const float* __restrict__ Wih2, const float* __restrict__ b2)
{
    extern __shared__ float sm[];
    float* Ws   = sm;            // [type][k][j], type 0:i 1:g 2:o
    float* hact = sm + 49152;    // [k][b]
    const int tid = threadIdx.x;
    const int bt  = blockIdx.x;

    for (int idx = tid; idx < 3 * 64 * 256; idx += 256) {
        int tt = idx >> 14;
        int r  = idx & 16383;
        int k  = r >> 8, j = r & 255;
        int o  = (tt == 0) ? 0 : (tt == 1) ? 512 : 768;  // i, g, o offsets
        Ws[idx] = __ldg(&Wih2[(size_t)(o + j) * 64 + k]);
    }
    for (int idx = tid; idx < 2048; idx += 256) {
        int bb = idx >> 6, k = idx & 63;
        hact[k * 32 + bb] = g_h64[(size_t)(bt * 32 + bb) * 64 + k];
    }
    __syncthreads();

    const int w = tid >> 5, l = tid & 31;
    for (int jc = 0; jc < 4; jc++) {
        int j = jc * 64 + 2 * l;
        ull bI = pk(__ldg(&b2[j]),       __ldg(&b2[j + 1]));
        ull bG = pk(__ldg(&b2[512 + j]), __ldg(&b2[512 + j + 1]));
        ull bO = pk(__ldg(&b2[768 + j]), __ldg(&b2[768 + j + 1]));
        ull aI[4], aG[4], aO[4];
        #pragma unroll
        for (int q = 0; q < 4; q++) { aI[q] = bI; aG[q] = bG; aO[q] = bO; }

        #pragma unroll 4
        for (int k = 0; k < 64; k++) {
            float4 a = *reinterpret_cast<const float4*>(hact + k * 32 + 4 * w);
            ull a0 = pk(a.x, a.x), a1 = pk(a.y, a.y);
            ull a2 = pk(a.z, a.z), a3 = pk(a.w, a.w);
            float2 wi = *reinterpret_cast<const float2*>(Ws + k * 256 + j);
            float2 wg = *reinterpret_cast<const float2*>(Ws + 16384 + k * 256 + j);
            float2 wo = *reinterpret_cast<const float2*>(Ws + 32768 + k * 256 + j);
            ull wpi = pk(wi.x, wi.y), wpg = pk(wg.x, wg.y), wpo = pk(wo.x, wo.y);
            fma2(aI[0], wpi, a0); fma2(aI[1], wpi, a1);
            fma2(aI[2], wpi, a2); fma2(aI[3], wpi, a3);
            fma2(aG[0], wpg, a0); fma2(aG[1], wpg, a1);
            fma2(aG[2], wpg, a2); fma2(aG[3], wpg, a3);
            fma2(aO[0], wpo, a0); fma2(aO[1], wpo, a1);
            fma2(aO[2], wpo, a2); fma2(aO[3], wpo, a3);
        }
        #pragma unroll
        for (int q = 0; q < 4; q++) {
            float2 vi = upk(aI[q]);
            float2 vg = upk(aG[q]);
            float2 vo = upk(aO[q]);
            float c0 = sigf(vi.x) * tanh_(vg.x);
            float h0 = sigf(vo.x) * tanh_(c0);
            float c1 = sigf(vi.y) * tanh_(vg.y);
            float h1 = sigf(vo.y) * tanh_(c1);
            int bb = bt * 32 + 4 * w + q;
            *reinterpret_cast<float2*>(&g_h256[(size_t)bb * 256 + j]) =
                make_float2(h0, h1);
        }
    }
}

// ---------------- output projection: out = h256 @ Wout^T + bout ----------------
__global__ void __launch_bounds__(256)
out_kernel(const float* __restrict__ Wout, const float* __restrict__ bout,
           float* __restrict__ out)
{
    int gw = (blockIdx.x * 256 + threadIdx.x) >> 5;   // one warp per batch elem
    int l  = threadIdx.x & 31;
    if (gw >= 4096) return;
    const float* hrow = g_h256 + (size_t)gw * 256;
    float p0 = 0.0f, p1 = 0.0f;
    #pragma unroll
    for (int m = 0; m < 8; m++) {
        int j = l + 32 * m;
        float h = hrow[j];
        p0 = fmaf(h, __ldg(&Wout[j]), p0);
        p1 = fmaf(h, __ldg(&Wout[256 + j]), p1);
    }
    #pragma unroll
    for (int s = 16; s > 0; s >>= 1) {
        p0 += __shfl_xor_sync(0xffffffffu, p0, s);
        p1 += __shfl_xor_sync(0xffffffffu, p1, s);
    }
    if (l == 0) {
        out[gw * 2]     = p0 + __ldg(&bout[0]);
        out[gw * 2 + 1] = p1 + __ldg(&bout[1]);
    }
}

// ---------------- launch ----------------
extern "C" void kernel_launch(void* const* d_in, const int* in_sizes, int n_in,
                              void* d_out, int out_size)
{
    const float *x = nullptr, *W_embed = nullptr, *Wih1 = nullptr, *Whh1 = nullptr,
                *b1 = nullptr, *Wih2 = nullptr, *b2 = nullptr,
                *Wout = nullptr, *bout = nullptr;
    for (int i = 0; i < n_in; i++) {
        const float* p = (const float*)d_in[i];
        switch (in_sizes[i]) {
            case 4194304: x = p; break;        // (4096, 1024)
            case 40:      W_embed = p; break;  // (20, 2)
            case 5120:    Wih1 = p; break;     // (256, 20)
            case 16384:   Whh1 = p; break;     // (256, 64)
            case 256:     b1 = p; break;       // (256,)
            case 65536:   Wih2 = p; break;     // (1024, 64)
            case 262144:  /* Whh2 unused */ break;
            case 1024:    b2 = p; break;       // (1024,)
            case 512:     Wout = p; break;     // (2, 256)
            case 2:       bout = p; break;     // (2,)
            default: break;
        }
    }
    float* out = (float*)d_out;

    const int SMEM1 = S_TOT * 4;              // 114176 B
    const int SMEM2 = (49152 + 2048) * 4;     // 204800 B
    cudaFuncSetAttribute(lstm1_kernel, cudaFuncAttributeMaxDynamicSharedMemorySize, SMEM1);
    cudaFuncSetAttribute(lstm2_kernel, cudaFuncAttributeMaxDynamicSharedMemorySize, SMEM2);

    lstm1_kernel<<<128, 256, SMEM1>>>(x, W_embed, Wih1, Whh1, b1);
    lstm2_kernel<<<128, 256, SMEM2>>>(Wih2, b2);
    out_kernel<<<512, 256>>>(Wout, bout, out);
    (void)out_size;
}